// round 1
// baseline (speedup 1.0000x reference)
#include <cuda_runtime.h>
#include <cstdint>
#include <math.h>

// ---------------- problem constants ----------------
#define Bn    8
#define Cn    512
#define Hn    64
#define Wn    64
#define HWn   4096          // 64*64
#define NTOK  32768         // 4096*8 tokens
#define LKH   256           // pooled seq len (16*16)
#define NKV   2048          // 256*8
#define C1n   358
#define C2n   154
#define HEADS 8
#define Dh    64

// ---------------- scratch (static device, no allocs) ----------------
__device__ float  g_qh_in[NTOK * Cn];
__device__ float  g_kv_in[NKV * Cn];
__device__ float  g_xv_in[NTOK * Cn];
__device__ float  g_qh   [NTOK * Cn];
__device__ float  g_kvh  [NKV * 2 * Cn];
__device__ float  g_qkvv [(size_t)NTOK * 3 * Cn];
__device__ float  g_oh   [NTOK * Cn];
__device__ float  g_ov   [NTOK * Cn];
__device__ float  g_ha   [(size_t)NTOK * C1n];
__device__ float  g_va   [(size_t)NTOK * C2n];
__device__ double g_stats[16];
__device__ float  g_mu[8];
__device__ float  g_rstd[8];

// ---------------- transpose x(b,c,h,w) -> token rows [row, C] ----------------
// mode 0 (horizontal): row = l*8 + b,  l = y*64 + x
// mode 1 (vertical):   row = (y*4+wd)*128 + b*16 + nwi,  x = nwi*4+wd
__global__ void transpose_kernel(const float* __restrict__ x,
                                 float* __restrict__ out, int mode)
{
    __shared__ float tile[32][33];
    int bb = blockIdx.z;
    int l0 = blockIdx.x * 32, c0 = blockIdx.y * 32;
    int tx = threadIdx.x, ty = threadIdx.y;   // (32, 8)
#pragma unroll
    for (int j = 0; j < 4; j++) {
        int c = c0 + ty + j * 8;
        tile[ty + j * 8][tx] = x[((size_t)(bb * Cn + c)) * HWn + l0 + tx];  // tile[cLocal][lLocal]
    }
    __syncthreads();
#pragma unroll
    for (int j = 0; j < 4; j++) {
        int l = l0 + ty + j * 8;
        int row;
        if (mode == 0) {
            row = l * Bn + bb;
        } else {
            int xx = l & 63, y = l >> 6;
            int wd = xx & 3, nwi = xx >> 2;
            row = y * 512 + wd * 128 + bb * 16 + nwi;
        }
        out[(size_t)row * Cn + c0 + tx] = tile[tx][ty + j * 8];
    }
}

// ---------------- 4x4 avg pool -> kv token rows [lk*8+b, C] ----------------
__global__ void pool_kernel(const float* __restrict__ x, float* __restrict__ out)
{
    int idx = blockIdx.x * 256 + threadIdx.x;
    if (idx >= Bn * Cn * 256) return;
    int px = idx & 15, py = (idx >> 4) & 15, c = (idx >> 8) & 511, bb = idx >> 17;
    const float* base = x + (((size_t)(bb * Cn + c)) * Hn + py * 4) * Wn + px * 4;
    float s = 0.f;
#pragma unroll
    for (int i = 0; i < 4; i++)
#pragma unroll
        for (int j = 0; j < 4; j++) s += base[i * Wn + j];
    out[((size_t)((py * 16 + px) * Bn + bb)) * Cn + c] = s * 0.0625f;
}

// ---------------- SGEMM:  C[orow(m), n] = sum_k A[m,k]*B[n,k] + bias[n] ----------------
// A row-major [M,K], B row-major [N,K] (weight layout), K % 16 == 0, M % 64 == 0.
// mode 1 permutes output rows for va_x layout.
__global__ __launch_bounds__(256) void sgemm_nt(
    const float* __restrict__ A, const float* __restrict__ Bm,
    const float* __restrict__ bias, float* __restrict__ Cc,
    int M, int N, int K, int ldc, int mode)
{
    __shared__ float As[16 * 64];
    __shared__ float Bs[16 * 64];
    int n0 = blockIdx.x * 64, m0 = blockIdx.y * 64;
    int tid = threadIdx.x;
    int tx = tid & 15, ty = tid >> 4;
    float acc[4][4];
#pragma unroll
    for (int i = 0; i < 4; i++)
#pragma unroll
        for (int j = 0; j < 4; j++) acc[i][j] = 0.f;

    int lrow = tid >> 2, lkq = tid & 3;
    const float4* A4 = (const float4*)A;
    const float4* B4 = (const float4*)Bm;
    int K4 = K >> 2;

    for (int k0 = 0; k0 < K; k0 += 16) {
        float4 av = A4[(size_t)(m0 + lrow) * K4 + (k0 >> 2) + lkq];
        float4 bv = make_float4(0.f, 0.f, 0.f, 0.f);
        int brow = n0 + lrow;
        if (brow < N) bv = B4[(size_t)brow * K4 + (k0 >> 2) + lkq];
        As[(lkq * 4 + 0) * 64 + lrow] = av.x;
        As[(lkq * 4 + 1) * 64 + lrow] = av.y;
        As[(lkq * 4 + 2) * 64 + lrow] = av.z;
        As[(lkq * 4 + 3) * 64 + lrow] = av.w;
        Bs[(lkq * 4 + 0) * 64 + lrow] = bv.x;
        Bs[(lkq * 4 + 1) * 64 + lrow] = bv.y;
        Bs[(lkq * 4 + 2) * 64 + lrow] = bv.z;
        Bs[(lkq * 4 + 3) * 64 + lrow] = bv.w;
        __syncthreads();
#pragma unroll
        for (int kk = 0; kk < 16; kk++) {
            float4 a = *(const float4*)&As[kk * 64 + ty * 4];
            float4 b = *(const float4*)&Bs[kk * 64 + tx * 4];
            acc[0][0] += a.x * b.x; acc[0][1] += a.x * b.y; acc[0][2] += a.x * b.z; acc[0][3] += a.x * b.w;
            acc[1][0] += a.y * b.x; acc[1][1] += a.y * b.y; acc[1][2] += a.y * b.z; acc[1][3] += a.y * b.w;
            acc[2][0] += a.z * b.x; acc[2][1] += a.z * b.y; acc[2][2] += a.z * b.z; acc[2][3] += a.z * b.w;
            acc[3][0] += a.w * b.x; acc[3][1] += a.w * b.y; acc[3][2] += a.w * b.z; acc[3][3] += a.w * b.w;
        }
        __syncthreads();
    }

    float bl[4];
#pragma unroll
    for (int j = 0; j < 4; j++) {
        int n = n0 + tx * 4 + j;
        bl[j] = (n < N) ? bias[n] : 0.f;
    }
#pragma unroll
    for (int i = 0; i < 4; i++) {
        int m = m0 + ty * 4 + i;
        int orow;
        if (mode == 0) {
            orow = m;
        } else {
            int nwi = m & 15, bb = (m >> 4) & 7, wd = (m >> 7) & 3, y = m >> 9;
            orow = ((y << 6) + (nwi << 2) + wd) * Bn + bb;
        }
        float* cr = Cc + (size_t)orow * ldc;
#pragma unroll
        for (int j = 0; j < 4; j++) {
            int n = n0 + tx * 4 + j;
            if (n < N) cr[n] = acc[i][j] + bl[j];
        }
    }
}

// ---------------- attention: one query per thread, K/V in smem ----------------
// element (l, b, head, d) at base[(l*Bt + b)*ld + head*64 + d]
__global__ __launch_bounds__(128) void attn_kernel(
    const float* __restrict__ qb, const float* __restrict__ kb,
    const float* __restrict__ vb, float* __restrict__ ob,
    int Lq, int Lk, int Bt, int qld, int kld, int oldd)
{
    extern __shared__ float sm[];
    int tid = threadIdx.x;
    int hd = blockIdx.y, bb = blockIdx.z;
    float4* Ks = (float4*)sm;
    float4* Vs = Ks + Lk * 16;
    for (int idx = tid; idx < Lk * 16; idx += 128) {
        int r = idx >> 4, cc = idx & 15;
        Ks[idx] = *(const float4*)(kb + (size_t)(r * Bt + bb) * kld + hd * 64 + cc * 4);
        Vs[idx] = *(const float4*)(vb + (size_t)(r * Bt + bb) * kld + hd * 64 + cc * 4);
    }
    __syncthreads();

    int qi = blockIdx.x * 128 + tid;
    if (qi >= Lq) return;
    const float* qrow = qb + (size_t)(qi * Bt + bb) * qld + hd * 64;
    float4 q4[16], acc[16];
#pragma unroll
    for (int i = 0; i < 16; i++) {
        q4[i]  = ((const float4*)qrow)[i];
        acc[i] = make_float4(0.f, 0.f, 0.f, 0.f);
    }
    float mmax = -1e30f, lsum = 0.f;
    for (int k = 0; k < Lk; k++) {
        const float4* kr = Ks + k * 16;
        float s = 0.f;
#pragma unroll
        for (int i = 0; i < 16; i++) {
            float4 kv = kr[i];
            s += q4[i].x * kv.x + q4[i].y * kv.y + q4[i].z * kv.z + q4[i].w * kv.w;
        }
        s *= 0.125f;   // 1/sqrt(64)
        float p;
        if (s > mmax) {
            float corr = __expf(mmax - s);
            mmax = s;
            lsum *= corr;
#pragma unroll
            for (int i = 0; i < 16; i++) {
                acc[i].x *= corr; acc[i].y *= corr; acc[i].z *= corr; acc[i].w *= corr;
            }
            p = 1.f;
        } else {
            p = __expf(s - mmax);
        }
        lsum += p;
        const float4* vr = Vs + k * 16;
#pragma unroll
        for (int i = 0; i < 16; i++) {
            float4 vv = vr[i];
            acc[i].x += p * vv.x; acc[i].y += p * vv.y;
            acc[i].z += p * vv.z; acc[i].w += p * vv.w;
        }
    }
    float inv = 1.f / lsum;
    float* orw = ob + (size_t)(qi * Bt + bb) * oldd + hd * 64;
#pragma unroll
    for (int i = 0; i < 16; i++) {
        float4 o = acc[i];
        o.x *= inv; o.y *= inv; o.z *= inv; o.w *= inv;
        ((float4*)orw)[i] = o;
    }
}

// ---------------- stats zero / concat+residual stats / finalize / normalize ----------------
__global__ void zero_stats_kernel()
{
    if (threadIdx.x < 16) g_stats[threadIdx.x] = 0.0;
}

__global__ void concat_stats_kernel(const float* __restrict__ x, float* __restrict__ attn_out)
{
    __shared__ float tile[32][33];
    int bb = blockIdx.z;
    int l0 = blockIdx.x * 32, c0 = blockIdx.y * 32;
    int tx = threadIdx.x, ty = threadIdx.y;   // (32, 8)
#pragma unroll
    for (int j = 0; j < 4; j++) {
        int c = c0 + tx;
        int l = l0 + ty + j * 8;
        int row = l * Bn + bb;
        float v = (c < C1n) ? g_ha[(size_t)row * C1n + c]
                            : g_va[(size_t)row * C2n + (c - C1n)];
        tile[ty + j * 8][tx] = v;     // tile[lLocal][cLocal]
    }
    __syncthreads();
    float lsum = 0.f, lsq = 0.f;
#pragma unroll
    for (int j = 0; j < 4; j++) {
        int c = c0 + ty + j * 8;
        int l = l0 + tx;
        float av = tile[tx][ty + j * 8];
        size_t gi = ((size_t)(bb * Cn + c)) * HWn + l;
        attn_out[gi] = av;
        float r = av + x[gi];
        lsum += r; lsq += r * r;
    }
#pragma unroll
    for (int off = 16; off > 0; off >>= 1) {
        lsum += __shfl_xor_sync(0xffffffffu, lsum, off);
        lsq  += __shfl_xor_sync(0xffffffffu, lsq,  off);
    }
    if (tx == 0) {
        atomicAdd(&g_stats[bb * 2 + 0], (double)lsum);
        atomicAdd(&g_stats[bb * 2 + 1], (double)lsq);
    }
}

__global__ void finalize_stats_kernel()
{
    int b = threadIdx.x;
    if (b < 8) {
        const double N = (double)Cn * HWn;     // 2097152
        double mu  = g_stats[2 * b + 0] / N;
        double var = g_stats[2 * b + 1] / N - mu * mu;
        g_mu[b]   = (float)mu;
        g_rstd[b] = (float)(1.0 / sqrt(var + 1e-5));
    }
}

__global__ void norm_kernel(const float* __restrict__ attn,
                            const float* __restrict__ x,
                            float* __restrict__ out)
{
    int i = blockIdx.x * 256 + threadIdx.x;
    int bb = i >> 21;                           // C*H*W = 2^21 per batch
    float r = attn[i] + x[i];
    out[i] = (r - g_mu[bb]) * g_rstd[bb];
}

// ---------------- host launcher ----------------
extern "C" void kernel_launch(void* const* d_in, const int* in_sizes, int n_in,
                              void* d_out, int out_size)
{
    const float* x       = (const float*)d_in[0];
    const float* h_in_w  = (const float*)d_in[1];
    const float* h_in_b  = (const float*)d_in[2];
    const float* h_out_w = (const float*)d_in[3];
    const float* h_out_b = (const float*)d_in[4];
    const float* v_in_w  = (const float*)d_in[5];
    const float* v_in_b  = (const float*)d_in[6];
    const float* v_out_w = (const float*)d_in[7];
    const float* v_out_b = (const float*)d_in[8];
    const float* hfc_w   = (const float*)d_in[9];
    const float* hfc_b   = (const float*)d_in[10];
    const float* vfc_w   = (const float*)d_in[11];
    const float* vfc_b   = (const float*)d_in[12];

    float* out      = (float*)d_out;
    float* out_res  = out;                                   // result   [b,C,h,w]
    float* out_hax  = out + (size_t)NTOK * Cn;               // ha_x     [h,w,b,c]
    float* out_vax  = out + 2 * (size_t)NTOK * Cn;           // va_x     [h,w,b,c]
    float* out_attn = out + 3 * (size_t)NTOK * Cn;           // attn     [b,C,h,w]

    float *p_qh_in, *p_kv_in, *p_xv_in, *p_qh, *p_kvh, *p_qkvv, *p_oh, *p_ov, *p_ha, *p_va;
    cudaGetSymbolAddress((void**)&p_qh_in, g_qh_in);
    cudaGetSymbolAddress((void**)&p_kv_in, g_kv_in);
    cudaGetSymbolAddress((void**)&p_xv_in, g_xv_in);
    cudaGetSymbolAddress((void**)&p_qh,    g_qh);
    cudaGetSymbolAddress((void**)&p_kvh,   g_kvh);
    cudaGetSymbolAddress((void**)&p_qkvv,  g_qkvv);
    cudaGetSymbolAddress((void**)&p_oh,    g_oh);
    cudaGetSymbolAddress((void**)&p_ov,    g_ov);
    cudaGetSymbolAddress((void**)&p_ha,    g_ha);
    cudaGetSymbolAddress((void**)&p_va,    g_va);

    dim3 tb(32, 8);

    // 1) layout transforms
    transpose_kernel<<<dim3(128, 16, 8), tb>>>(x, p_qh_in, 0);
    transpose_kernel<<<dim3(128, 16, 8), tb>>>(x, p_xv_in, 1);
    pool_kernel<<<(Bn * Cn * 256 + 255) / 256, 256>>>(x, p_kv_in);

    // 2) input projections
    sgemm_nt<<<dim3(8, 512), 256>>>(p_qh_in, h_in_w,            h_in_b,       p_qh,   NTOK, 512,  512, 512,  0);
    sgemm_nt<<<dim3(16, 32), 256>>>(p_kv_in, h_in_w + 512*512,  h_in_b + 512, p_kvh,  NKV,  1024, 512, 1024, 0);
    sgemm_nt<<<dim3(24, 512), 256>>>(p_xv_in, v_in_w,           v_in_b,       p_qkvv, NTOK, 1536, 512, 1536, 0);

    // 3) attention
    int smem = 2 * 256 * 64 * (int)sizeof(float);   // 128 KB K+V
    cudaFuncSetAttribute(attn_kernel, cudaFuncAttributeMaxDynamicSharedMemorySize, smem);
    attn_kernel<<<dim3(32, 8, 8),   128, smem>>>(p_qh,   p_kvh,        p_kvh + 512,   p_oh, 4096, 256, 8,   512,  1024, 512);
    attn_kernel<<<dim3(2, 8, 128),  128, smem>>>(p_qkvv, p_qkvv + 512, p_qkvv + 1024, p_ov, 256,  256, 128, 1536, 1536, 512);

    // 4) output projections (write ha_x / va_x straight into d_out regions)
    sgemm_nt<<<dim3(8, 512), 256>>>(p_oh, h_out_w, h_out_b, out_hax, NTOK, 512, 512, 512, 0);
    sgemm_nt<<<dim3(8, 512), 256>>>(p_ov, v_out_w, v_out_b, out_vax, NTOK, 512, 512, 512, 1);

    // 5) fc heads (read ha_x/va_x back from d_out)
    sgemm_nt<<<dim3(6, 512), 256>>>(out_hax, hfc_w, hfc_b, p_ha, NTOK, C1n, 512, C1n, 0);
    sgemm_nt<<<dim3(3, 512), 256>>>(out_vax, vfc_w, vfc_b, p_va, NTOK, C2n, 512, C2n, 0);

    // 6) concat + residual stats + layernorm
    zero_stats_kernel<<<1, 32>>>();
    concat_stats_kernel<<<dim3(128, 16, 8), tb>>>(x, out_attn);
    finalize_stats_kernel<<<1, 32>>>();
    norm_kernel<<<NTOK * Cn / 256, 256>>>(out_attn, x, out_res);
}

// round 2
// speedup vs baseline: 1.9389x; 1.9389x over previous
#include <cuda_runtime.h>
#include <cstdint>
#include <math.h>

// ---------------- problem constants ----------------
#define Bn    8
#define Cn    512
#define Hn    64
#define Wn    64
#define HWn   4096          // 64*64
#define NTOK  32768         // 4096*8 tokens
#define NKV   2048          // 256*8
#define C1n   358
#define C2n   154

// ---------------- scratch (static device, no allocs) ----------------
__device__ float  g_qh_in[NTOK * Cn];
__device__ float  g_kv_in[NKV * Cn];
__device__ float  g_xv_in[NTOK * Cn];
__device__ float  g_qh   [NTOK * Cn];
__device__ float  g_kvh  [NKV * 2 * Cn];
__device__ float  g_qkvv [(size_t)NTOK * 3 * Cn];
__device__ float  g_oh   [NTOK * Cn];
__device__ float  g_ov   [NTOK * Cn];
__device__ float  g_ha   [(size_t)NTOK * C1n];
__device__ float  g_va   [(size_t)NTOK * C2n];
__device__ double g_stats[16];
__device__ float  g_mu[8];
__device__ float  g_rstd[8];

// ---------------- transpose x(b,c,h,w) -> token rows [row, C] ----------------
__global__ void transpose_kernel(const float* __restrict__ x,
                                 float* __restrict__ out, int mode)
{
    __shared__ float tile[32][33];
    int bb = blockIdx.z;
    int l0 = blockIdx.x * 32, c0 = blockIdx.y * 32;
    int tx = threadIdx.x, ty = threadIdx.y;   // (32, 8)
#pragma unroll
    for (int j = 0; j < 4; j++) {
        int c = c0 + ty + j * 8;
        tile[ty + j * 8][tx] = x[((size_t)(bb * Cn + c)) * HWn + l0 + tx];
    }
    __syncthreads();
#pragma unroll
    for (int j = 0; j < 4; j++) {
        int l = l0 + ty + j * 8;
        int row;
        if (mode == 0) {
            row = l * Bn + bb;
        } else {
            int xx = l & 63, y = l >> 6;
            int wd = xx & 3, nwi = xx >> 2;
            row = y * 512 + wd * 128 + bb * 16 + nwi;
        }
        out[(size_t)row * Cn + c0 + tx] = tile[tx][ty + j * 8];
    }
}

// ---------------- 4x4 avg pool -> kv token rows [lk*8+b, C] ----------------
__global__ void pool_kernel(const float* __restrict__ x, float* __restrict__ out)
{
    int idx = blockIdx.x * 256 + threadIdx.x;
    if (idx >= Bn * Cn * 256) return;
    int px = idx & 15, py = (idx >> 4) & 15, c = (idx >> 8) & 511, bb = idx >> 17;
    const float* base = x + (((size_t)(bb * Cn + c)) * Hn + py * 4) * Wn + px * 4;
    float s = 0.f;
#pragma unroll
    for (int i = 0; i < 4; i++)
#pragma unroll
        for (int j = 0; j < 4; j++) s += base[i * Wn + j];
    out[((size_t)((py * 16 + px) * Bn + bb)) * Cn + c] = s * 0.0625f;
}

// ---------------- tf32 helpers ----------------
__device__ __forceinline__ unsigned f2tf(float f) {
    unsigned r;
    asm("cvt.rna.tf32.f32 %0, %1;" : "=r"(r) : "f"(f));
    return r;
}

__device__ __forceinline__ void mma_tf32(float acc[4], const unsigned a[4], const unsigned b[2]) {
    asm volatile(
        "mma.sync.aligned.m16n8k8.row.col.f32.tf32.tf32.f32 "
        "{%0,%1,%2,%3}, {%4,%5,%6,%7}, {%8,%9}, {%0,%1,%2,%3};\n"
        : "+f"(acc[0]), "+f"(acc[1]), "+f"(acc[2]), "+f"(acc[3])
        : "r"(a[0]), "r"(a[1]), "r"(a[2]), "r"(a[3]), "r"(b[0]), "r"(b[1]));
}

// ---------------- tf32 tensor-core GEMM:  C[orow(m), n] = A[m,:]·B[n,:] + bias[n] ----
// A row-major [M,K], B row-major [N,K]. M % 128 == 0, K % 32 == 0. N arbitrary (even).
// CTA tile 128x64, 8 warps in 4(m) x 2(n), warp tile 32x32, K-chunk 32.
__global__ __launch_bounds__(256) void sgemm_tf32(
    const float* __restrict__ A, const float* __restrict__ Bm,
    const float* __restrict__ bias, float* __restrict__ Cc,
    int M, int N, int K, int ldc, int mode)
{
    __shared__ unsigned As[128][36];   // [m][k], pad 4 -> conflict-free frag loads
    __shared__ unsigned Bs[64][36];    // [n][k]

    int tid  = threadIdx.x;
    int warp = tid >> 5, lane = tid & 31;
    int wm = warp & 3, wn = warp >> 1 & 0 ? 0 : (warp >> 2);  // wm in 0..3, wn in 0..1
    wn = warp >> 2;
    int g = lane >> 2, t = lane & 3;
    int m0 = blockIdx.y * 128, n0 = blockIdx.x * 64;

    float acc[2][4][4];
#pragma unroll
    for (int mi = 0; mi < 2; mi++)
#pragma unroll
        for (int ni = 0; ni < 4; ni++)
#pragma unroll
            for (int j = 0; j < 4; j++) acc[mi][ni][j] = 0.f;

    int arow = tid >> 3;             // 0..31
    int ac   = (tid & 7) * 4;        // float4 col within 32
    int brow = tid >> 2;             // 0..63
    int bc0  = (tid & 3) * 4;        // two float4s at bc0 and bc0+16

    for (int k0 = 0; k0 < K; k0 += 32) {
        // stage A (128x32)
#pragma unroll
        for (int i = 0; i < 4; i++) {
            int r = arow + i * 32;
            float4 v = *(const float4*)(A + (size_t)(m0 + r) * K + k0 + ac);
            As[r][ac + 0] = f2tf(v.x); As[r][ac + 1] = f2tf(v.y);
            As[r][ac + 2] = f2tf(v.z); As[r][ac + 3] = f2tf(v.w);
        }
        // stage B (64x32), zero-fill rows >= N
#pragma unroll
        for (int i = 0; i < 2; i++) {
            int c = bc0 + i * 16;
            float4 v = make_float4(0.f, 0.f, 0.f, 0.f);
            if (n0 + brow < N)
                v = *(const float4*)(Bm + (size_t)(n0 + brow) * K + k0 + c);
            Bs[brow][c + 0] = f2tf(v.x); Bs[brow][c + 1] = f2tf(v.y);
            Bs[brow][c + 2] = f2tf(v.z); Bs[brow][c + 3] = f2tf(v.w);
        }
        __syncthreads();

#pragma unroll
        for (int kk = 0; kk < 32; kk += 8) {
            unsigned af[2][4], bf[4][2];
#pragma unroll
            for (int mi = 0; mi < 2; mi++) {
                int rm = wm * 32 + mi * 16 + g;
                af[mi][0] = As[rm    ][kk + t];
                af[mi][1] = As[rm + 8][kk + t];
                af[mi][2] = As[rm    ][kk + t + 4];
                af[mi][3] = As[rm + 8][kk + t + 4];
            }
#pragma unroll
            for (int ni = 0; ni < 4; ni++) {
                int rn = wn * 32 + ni * 8 + g;
                bf[ni][0] = Bs[rn][kk + t];
                bf[ni][1] = Bs[rn][kk + t + 4];
            }
#pragma unroll
            for (int mi = 0; mi < 2; mi++)
#pragma unroll
                for (int ni = 0; ni < 4; ni++)
                    mma_tf32(acc[mi][ni], af[mi], bf[ni]);
        }
        __syncthreads();
    }

    // epilogue: C row = lane/4 (+8), col = ni*8 + 2*(lane%4) + {0,1}
#pragma unroll
    for (int mi = 0; mi < 2; mi++) {
#pragma unroll
        for (int half = 0; half < 2; half++) {
            int m = m0 + wm * 32 + mi * 16 + g + half * 8;
            int orow;
            if (mode == 0) {
                orow = m;
            } else {
                int nwi = m & 15, bb = (m >> 4) & 7, wd = (m >> 7) & 3, y = m >> 9;
                orow = ((y << 6) + (nwi << 2) + wd) * Bn + bb;
            }
            float* cr = Cc + (size_t)orow * ldc;
#pragma unroll
            for (int ni = 0; ni < 4; ni++) {
                int n = n0 + wn * 32 + ni * 8 + t * 2;
                if (n < N) {
                    cr[n]     = acc[mi][ni][half * 2 + 0] + bias[n];
                    cr[n + 1] = acc[mi][ni][half * 2 + 1] + bias[n + 1];
                }
            }
        }
    }
}

// ---------------- attention: one query per thread, K/V in smem (256 thr) ------
__global__ __launch_bounds__(256, 1) void attn_kernel(
    const float* __restrict__ qb, const float* __restrict__ kb,
    const float* __restrict__ vb, float* __restrict__ ob,
    int Lq, int Lk, int Bt, int qld, int kld, int oldd)
{
    extern __shared__ float sm[];
    int tid = threadIdx.x;
    int hd = blockIdx.y, bb = blockIdx.z;
    float4* Ks = (float4*)sm;
    float4* Vs = Ks + Lk * 16;
    for (int idx = tid; idx < Lk * 16; idx += 256) {
        int r = idx >> 4, cc = idx & 15;
        Ks[idx] = *(const float4*)(kb + (size_t)(r * Bt + bb) * kld + hd * 64 + cc * 4);
        Vs[idx] = *(const float4*)(vb + (size_t)(r * Bt + bb) * kld + hd * 64 + cc * 4);
    }
    __syncthreads();

    int qi = blockIdx.x * 256 + tid;
    if (qi >= Lq) return;
    const float* qrow = qb + (size_t)(qi * Bt + bb) * qld + hd * 64;
    float4 q4[16], acc[16];
#pragma unroll
    for (int i = 0; i < 16; i++) {
        q4[i]  = ((const float4*)qrow)[i];
        acc[i] = make_float4(0.f, 0.f, 0.f, 0.f);
    }
    float mmax = -1e30f, lsum = 0.f;
    for (int k = 0; k < Lk; k++) {
        const float4* kr = Ks + k * 16;
        float s = 0.f;
#pragma unroll
        for (int i = 0; i < 16; i++) {
            float4 kv = kr[i];
            s += q4[i].x * kv.x + q4[i].y * kv.y + q4[i].z * kv.z + q4[i].w * kv.w;
        }
        s *= 0.125f;   // 1/sqrt(64)
        float p;
        if (s > mmax) {
            float corr = __expf(mmax - s);
            mmax = s;
            lsum *= corr;
#pragma unroll
            for (int i = 0; i < 16; i++) {
                acc[i].x *= corr; acc[i].y *= corr; acc[i].z *= corr; acc[i].w *= corr;
            }
            p = 1.f;
        } else {
            p = __expf(s - mmax);
        }
        lsum += p;
        const float4* vr = Vs + k * 16;
#pragma unroll
        for (int i = 0; i < 16; i++) {
            float4 vv = vr[i];
            acc[i].x += p * vv.x; acc[i].y += p * vv.y;
            acc[i].z += p * vv.z; acc[i].w += p * vv.w;
        }
    }
    float inv = 1.f / lsum;
    float* orw = ob + (size_t)(qi * Bt + bb) * oldd + hd * 64;
#pragma unroll
    for (int i = 0; i < 16; i++) {
        float4 o = acc[i];
        o.x *= inv; o.y *= inv; o.z *= inv; o.w *= inv;
        ((float4*)orw)[i] = o;
    }
}

// ---------------- stats / concat / normalize ----------------
__global__ void zero_stats_kernel()
{
    if (threadIdx.x < 16) g_stats[threadIdx.x] = 0.0;
}

__global__ void concat_stats_kernel(const float* __restrict__ x, float* __restrict__ attn_out)
{
    __shared__ float tile[32][33];
    int bb = blockIdx.z;
    int l0 = blockIdx.x * 32, c0 = blockIdx.y * 32;
    int tx = threadIdx.x, ty = threadIdx.y;   // (32, 8)
#pragma unroll
    for (int j = 0; j < 4; j++) {
        int c = c0 + tx;
        int l = l0 + ty + j * 8;
        int row = l * Bn + bb;
        float v = (c < C1n) ? g_ha[(size_t)row * C1n + c]
                            : g_va[(size_t)row * C2n + (c - C1n)];
        tile[ty + j * 8][tx] = v;
    }
    __syncthreads();
    float lsum = 0.f, lsq = 0.f;
#pragma unroll
    for (int j = 0; j < 4; j++) {
        int c = c0 + ty + j * 8;
        int l = l0 + tx;
        float av = tile[tx][ty + j * 8];
        size_t gi = ((size_t)(bb * Cn + c)) * HWn + l;
        attn_out[gi] = av;
        float r = av + x[gi];
        lsum += r; lsq += r * r;
    }
#pragma unroll
    for (int off = 16; off > 0; off >>= 1) {
        lsum += __shfl_xor_sync(0xffffffffu, lsum, off);
        lsq  += __shfl_xor_sync(0xffffffffu, lsq,  off);
    }
    if (tx == 0) {
        atomicAdd(&g_stats[bb * 2 + 0], (double)lsum);
        atomicAdd(&g_stats[bb * 2 + 1], (double)lsq);
    }
}

__global__ void finalize_stats_kernel()
{
    int b = threadIdx.x;
    if (b < 8) {
        const double N = (double)Cn * HWn;
        double mu  = g_stats[2 * b + 0] / N;
        double var = g_stats[2 * b + 1] / N - mu * mu;
        g_mu[b]   = (float)mu;
        g_rstd[b] = (float)(1.0 / sqrt(var + 1e-5));
    }
}

__global__ void norm_kernel(const float* __restrict__ attn,
                            const float* __restrict__ x,
                            float* __restrict__ out)
{
    int i = blockIdx.x * 256 + threadIdx.x;
    int bb = i >> 21;
    float r = attn[i] + x[i];
    out[i] = (r - g_mu[bb]) * g_rstd[bb];
}

// ---------------- host launcher ----------------
extern "C" void kernel_launch(void* const* d_in, const int* in_sizes, int n_in,
                              void* d_out, int out_size)
{
    const float* x       = (const float*)d_in[0];
    const float* h_in_w  = (const float*)d_in[1];
    const float* h_in_b  = (const float*)d_in[2];
    const float* h_out_w = (const float*)d_in[3];
    const float* h_out_b = (const float*)d_in[4];
    const float* v_in_w  = (const float*)d_in[5];
    const float* v_in_b  = (const float*)d_in[6];
    const float* v_out_w = (const float*)d_in[7];
    const float* v_out_b = (const float*)d_in[8];
    const float* hfc_w   = (const float*)d_in[9];
    const float* hfc_b   = (const float*)d_in[10];
    const float* vfc_w   = (const float*)d_in[11];
    const float* vfc_b   = (const float*)d_in[12];

    float* out      = (float*)d_out;
    float* out_res  = out;                                   // result   [b,C,h,w]
    float* out_hax  = out + (size_t)NTOK * Cn;               // ha_x     [h,w,b,c]
    float* out_vax  = out + 2 * (size_t)NTOK * Cn;           // va_x     [h,w,b,c]
    float* out_attn = out + 3 * (size_t)NTOK * Cn;           // attn     [b,C,h,w]

    float *p_qh_in, *p_kv_in, *p_xv_in, *p_qh, *p_kvh, *p_qkvv, *p_oh, *p_ov, *p_ha, *p_va;
    cudaGetSymbolAddress((void**)&p_qh_in, g_qh_in);
    cudaGetSymbolAddress((void**)&p_kv_in, g_kv_in);
    cudaGetSymbolAddress((void**)&p_xv_in, g_xv_in);
    cudaGetSymbolAddress((void**)&p_qh,    g_qh);
    cudaGetSymbolAddress((void**)&p_kvh,   g_kvh);
    cudaGetSymbolAddress((void**)&p_qkvv,  g_qkvv);
    cudaGetSymbolAddress((void**)&p_oh,    g_oh);
    cudaGetSymbolAddress((void**)&p_ov,    g_ov);
    cudaGetSymbolAddress((void**)&p_ha,    g_ha);
    cudaGetSymbolAddress((void**)&p_va,    g_va);

    dim3 tb(32, 8);

    // 1) layout transforms
    transpose_kernel<<<dim3(128, 16, 8), tb>>>(x, p_qh_in, 0);
    transpose_kernel<<<dim3(128, 16, 8), tb>>>(x, p_xv_in, 1);
    pool_kernel<<<(Bn * Cn * 256 + 255) / 256, 256>>>(x, p_kv_in);

    // 2) input projections (tf32 tensor cores)
    sgemm_tf32<<<dim3(8, 256), 256>>>(p_qh_in, h_in_w,           h_in_b,       p_qh,   NTOK, 512,  512, 512,  0);
    sgemm_tf32<<<dim3(16, 16), 256>>>(p_kv_in, h_in_w + 512*512, h_in_b + 512, p_kvh,  NKV,  1024, 512, 1024, 0);
    sgemm_tf32<<<dim3(24, 256), 256>>>(p_xv_in, v_in_w,          v_in_b,       p_qkvv, NTOK, 1536, 512, 1536, 0);

    // 3) attention
    int smem = 2 * 256 * 64 * (int)sizeof(float);   // 128 KB K+V
    cudaFuncSetAttribute(attn_kernel, cudaFuncAttributeMaxDynamicSharedMemorySize, smem);
    attn_kernel<<<dim3(16, 8, 8),  256, smem>>>(p_qh,   p_kvh,        p_kvh + 512,   p_oh, 4096, 256, 8,   512,  1024, 512);
    attn_kernel<<<dim3(1, 8, 128), 256, smem>>>(p_qkvv, p_qkvv + 512, p_qkvv + 1024, p_ov, 256,  256, 128, 1536, 1536, 512);

    // 4) output projections
    sgemm_tf32<<<dim3(8, 256), 256>>>(p_oh, h_out_w, h_out_b, out_hax, NTOK, 512, 512, 512, 0);
    sgemm_tf32<<<dim3(8, 256), 256>>>(p_ov, v_out_w, v_out_b, out_vax, NTOK, 512, 512, 512, 1);

    // 5) fc heads
    sgemm_tf32<<<dim3(6, 256), 256>>>(out_hax, hfc_w, hfc_b, p_ha, NTOK, C1n, 512, C1n, 0);
    sgemm_tf32<<<dim3(3, 256), 256>>>(out_vax, vfc_w, vfc_b, p_va, NTOK, C2n, 512, C2n, 0);

    // 6) concat + residual stats + layernorm
    zero_stats_kernel<<<1, 32>>>();
    concat_stats_kernel<<<dim3(128, 16, 8), tb>>>(x, out_attn);
    finalize_stats_kernel<<<1, 32>>>();
    norm_kernel<<<NTOK * Cn / 256, 256>>>(out_attn, x, out_res);
}